// round 2
// baseline (speedup 1.0000x reference)
#include <cuda_runtime.h>
#include <cuda_bf16.h>
#include <cstdint>

#define BSZ  16
#define CCH  64
#define LSEQ 36864
#define DM   16
#define DI   32
#define DS   16
#define NSEQ 64
#define COUT 48

#define NCH  24
#define CSZ  1536          // LSEQ / NCH
#define WARM 256
#define TILE 16
#define WPB  4
#define NB1  288           // LSEQ / 128

// ---------------- scratch (device globals; no runtime allocation) ------------
__device__ float g_un[(size_t)NSEQ * LSEQ * DM];    // normalized grouped input
__device__ float g_q [(size_t)NSEQ * LSEQ * DI];    // pre-out-proj mamba result
__device__ float g_unpart[BSZ * NB1 * CCH];
__device__ float g_qpart [NSEQ * NCH * DI];
__device__ float g_unsum [NSEQ * DM];
__device__ float g_gate  [NSEQ * DI];
__device__ float g_A [DI * DS];
__device__ float g_a0[DI];
__device__ int   g_struct;

__device__ __forceinline__ float sigf(float v) {
    return __fdividef(1.f, 1.f + __expf(-v));
}

// ---------------- prep: A = -exp(A_log), detect power structure --------------
__global__ void k_prep(const float* __restrict__ A_log) {
    int d = threadIdx.x;  // 32 threads
    float a[DS];
#pragma unroll
    for (int n = 0; n < DS; n++) {
        a[n] = -expf(A_log[d * DS + n]);
        g_A[d * DS + n] = a[n];
    }
    g_a0[d] = a[0];
    int good = 1;
#pragma unroll
    for (int n = 0; n < DS; n++) {
        float r = a[0] * (float)(n + 1);
        if (fabsf(a[n] - r) > 1e-4f * fmaxf(1.f, fabsf(r))) good = 0;
    }
    int allok = __syncthreads_and(good);
    if (d == 0) g_struct = allok;
}

// ---------------- pass 1: layernorm + regroup + skip partial sums ------------
__global__ void __launch_bounds__(128) k_ln1(const float* __restrict__ x,
                                             const float* __restrict__ ng,
                                             const float* __restrict__ nb) {
    __shared__ float tile[CCH][129];
    __shared__ float sM[128], sR[128];
    __shared__ float sG[CCH], sB[CCH];
    int t = threadIdx.x, blk = blockIdx.x, b = blockIdx.y;
    if (t < CCH) { sG[t] = ng[t]; sB[t] = nb[t]; }

    const float* xb = x + (size_t)b * CCH * LSEQ + (size_t)blk * 128;
    float sum = 0.f, sq = 0.f;
#pragma unroll 4
    for (int c = 0; c < CCH; c++) {
        float v = xb[(size_t)c * LSEQ + t];
        tile[c][t] = v;
        sum += v;
        sq = fmaf(v, v, sq);
    }
    float mean = sum * (1.f / 64.f);
    float var  = sq * (1.f / 64.f) - mean * mean;
    sM[t] = mean;
    sR[t] = rsqrtf(var + 1e-5f);
    __syncthreads();

#pragma unroll
    for (int g = 0; g < 4; g++) {
        float* ob = g_un + ((size_t)(g * 16 + b) * LSEQ + (size_t)blk * 128) * DM;
#pragma unroll 4
        for (int rep = 0; rep < 16; rep++) {
            int idx = rep * 128 + t;
            int l = idx >> 4, j = idx & 15;
            int c = g * 16 + j;
            ob[idx] = (tile[c][l] - sM[l]) * sR[l] * sG[c] + sB[c];
        }
    }
    if (t < CCH) {
        float a = 0.f;
#pragma unroll 4
        for (int l = 0; l < 128; l++) a += (tile[t][l] - sM[l]) * sR[l];
        g_unpart[((size_t)b * NB1 + blk) * CCH + t] = a * sG[t] + 128.f * sB[t];
    }
}

// ---------------- reduce skip-path partials ----------------------------------
__global__ void k_red1() {
    int id = blockIdx.x * 256 + threadIdx.x;
    if (id >= NSEQ * DM) return;
    int s = id >> 4, j = id & 15;
    int b = s & 15, g = s >> 4;
    float a = 0.f;
    for (int blk = 0; blk < NB1; blk++)
        a += g_unpart[((size_t)b * NB1 + blk) * CCH + g * 16 + j];
    g_unsum[id] = a;
}

// ---------------- pass 2: mamba (in-proj + conv + xproj + selective scan) ----
__global__ void __launch_bounds__(128) k_scan(
    const float* __restrict__ in_w,     const float* __restrict__ conv_w,
    const float* __restrict__ conv_b,   const float* __restrict__ xproj_w,
    const float* __restrict__ dtproj_w, const float* __restrict__ dtproj_b,
    const float* __restrict__ Dp)
{
    __shared__ float w_in[64][16];
    __shared__ float w_xp[33][32];
    __shared__ float w_cv[32][4];
    __shared__ float b_cv[32];
    __shared__ float sXpre[WPB][TILE + 3][33];
    __shared__ float sAct [WPB][TILE][33];
    __shared__ float sZs  [WPB][TILE][33];
    __shared__ float sBC  [WPB][TILE][36];
    __shared__ float sDt  [WPB][TILE];

    int tid = threadIdx.x, wid = tid >> 5, lane = tid & 31;
    for (int i = tid; i < 64 * 16; i += 128) w_in[i >> 4][i & 15] = in_w[i];
    for (int i = tid; i < 33 * 32; i += 128) w_xp[i >> 5][i & 31] = xproj_w[i];
    if (tid < 32) {
#pragma unroll
        for (int k = 0; k < 4; k++) w_cv[tid][k] = conv_w[tid * 4 + k];
        b_cv[tid] = conv_b[tid];
    }
    __syncthreads();

    int job = blockIdx.x * WPB + wid;          // 0..1535
    int s = job / NCH, ch = job - s * NCH;
    int qstart = ch * CSZ;
    int start  = (qstart >= WARM) ? (qstart - WARM) : 0;
    int nsteps = qstart + CSZ - start;         // multiple of TILE
    int woff   = qstart - start;
    const float* uBase = g_un + ((size_t)s * LSEQ + start) * DM;
    float*       qBase = g_q  + ((size_t)s * LSEQ + start) * DI;

    // phase-B per-lane weights (lane = d channel)
    float dtw = dtproj_w[lane], dtb = dtproj_b[lane];
    float Dd = Dp[lane], a0 = g_a0[lane];
    float Arow[DS];
#pragma unroll
    for (int n = 0; n < DS; n++) Arow[n] = g_A[lane * DS + n];
    int structured = g_struct;
    float h[DS];
#pragma unroll
    for (int n = 0; n < DS; n++) h[n] = 0.f;
    float qsum = 0.f;

#pragma unroll
    for (int r = 0; r < 3; r++) sXpre[wid][r][lane] = 0.f;   // conv zero-pad
    __syncwarp();

    int t16 = lane >> 1, hf = lane & 1;        // phase-A roles: lane pair per t
    int dbase = hf * 16;

    for (int tb = 0; tb < nsteps; tb += TILE) {
        // ---- phase A1: in-projection (x pre-conv + silu(z)) ----
        {
            const float4* u4 = (const float4*)(uBase + (size_t)(tb + t16) * DM);
            float4 ua = u4[0], ub = u4[1], uc = u4[2], ud = u4[3];
            float uu[16] = {ua.x, ua.y, ua.z, ua.w, ub.x, ub.y, ub.z, ub.w,
                            uc.x, uc.y, uc.z, uc.w, ud.x, ud.y, ud.z, ud.w};
#pragma unroll 4
            for (int j = 0; j < 16; j++) {
                int dx = dbase + j;
                float ax = 0.f, az = 0.f;
#pragma unroll
                for (int k = 0; k < 16; k++) {
                    ax = fmaf(uu[k], w_in[dx][k], ax);
                    az = fmaf(uu[k], w_in[32 + dx][k], az);
                }
                sXpre[wid][3 + t16][dx] = ax;
                sZs[wid][t16][dx] = az * sigf(az);
            }
        }
        __syncwarp();
        // ---- phase A2: depthwise causal conv + silu ----
        {
#pragma unroll 4
            for (int j = 0; j < 16; j++) {
                int dx = dbase + j;
                float acc = b_cv[dx];
#pragma unroll
                for (int k = 0; k < 4; k++)
                    acc = fmaf(w_cv[dx][k], sXpre[wid][t16 + k][dx], acc);
                sAct[wid][t16][dx] = acc * sigf(acc);
            }
        }
        __syncwarp();
        // ---- phase A3: x-projection -> dt_raw, B, C ----
        {
            float o[33];
#pragma unroll
            for (int jj = 0; jj < 33; jj++) o[jj] = 0.f;
#pragma unroll 4
            for (int j = 0; j < 16; j++) {
                int dx = dbase + j;
                float xv = sAct[wid][t16][dx];
#pragma unroll
                for (int jj = 0; jj < 33; jj++)
                    o[jj] = fmaf(xv, w_xp[jj][dx], o[jj]);
            }
#pragma unroll
            for (int jj = 0; jj < 33; jj++)
                o[jj] += __shfl_xor_sync(0xffffffffu, o[jj], 1);
            if (hf == 0) {
                sDt[wid][t16] = o[0];
#pragma unroll
                for (int n = 0; n < 16; n++) sBC[wid][t16][n] = o[1 + n];
            } else {
#pragma unroll
                for (int n = 0; n < 16; n++) sBC[wid][t16][16 + n] = o[17 + n];
            }
        }
        __syncwarp();
        // ---- phase B: selective scan (lane = d) ----
        {
            int d = lane;
#pragma unroll 2
            for (int tt = 0; tt < TILE; tt++) {
                float dtraw = sDt[wid][tt];
                float pre = fmaf(dtraw, dtw, dtb);
                float dt = (pre > 20.f) ? pre : __logf(1.f + __expf(pre));
                float xv = sAct[wid][tt][d];
                float zs = sZs[wid][tt][d];
                float bx = dt * xv;
                const float4* bc = (const float4*)&sBC[wid][tt][0];
                float4 B0 = bc[0], B1 = bc[1], B2 = bc[2], B3 = bc[3];
                float4 C0 = bc[4], C1 = bc[5], C2 = bc[6], C3 = bc[7];
                float Bv[16] = {B0.x, B0.y, B0.z, B0.w, B1.x, B1.y, B1.z, B1.w,
                                B2.x, B2.y, B2.z, B2.w, B3.x, B3.y, B3.z, B3.w};
                float Cv[16] = {C0.x, C0.y, C0.z, C0.w, C1.x, C1.y, C1.z, C1.w,
                                C2.x, C2.y, C2.z, C2.w, C3.x, C3.y, C3.z, C3.w};
                float y = 0.f;
                if (structured) {
                    float p = __expf(dt * a0);
                    float pw = p;
#pragma unroll
                    for (int n = 0; n < 16; n++) {
                        h[n] = fmaf(pw, h[n], bx * Bv[n]);
                        y = fmaf(h[n], Cv[n], y);
                        pw *= p;
                    }
                } else {
#pragma unroll
                    for (int n = 0; n < 16; n++) {
                        h[n] = fmaf(__expf(dt * Arow[n]), h[n], bx * Bv[n]);
                        y = fmaf(h[n], Cv[n], y);
                    }
                }
                int t = tb + tt;
                if (t >= woff) {
                    float q = fmaf(Dd, xv, y) * zs;
                    qBase[(size_t)t * DI + d] = q;
                    qsum += q;
                }
            }
        }
        __syncwarp();
#pragma unroll
        for (int r = 0; r < 3; r++)
            sXpre[wid][r][lane] = sXpre[wid][TILE + r][lane];   // conv carry
        __syncwarp();
    }
    g_qpart[(s * NCH + ch) * DI + lane] = qsum;
}

// ---------------- SE gate ----------------------------------------------------
__global__ void k_se(const float* __restrict__ se_w1, const float* __restrict__ se_w2,
                     const float* __restrict__ out_w, const float* __restrict__ skip) {
    int s = threadIdx.x;
    if (s >= NSEQ) return;
    float qs[DI];
#pragma unroll 4
    for (int d = 0; d < DI; d++) {
        float a = 0.f;
        for (int ch = 0; ch < NCH; ch++) a += g_qpart[(s * NCH + ch) * DI + d];
        qs[d] = a * (1.f / (float)LSEQ);
    }
    float avg[32];
    for (int j = 0; j < 16; j++) {
        float m = 0.f;
        for (int d = 0; d < DI; d++) m = fmaf(qs[d], out_w[j * DI + d], m);
        avg[j] = m;
    }
    float sk = skip[0];
    for (int j = 0; j < 16; j++)
        avg[16 + j] = sk * g_unsum[s * 16 + j] * (1.f / (float)LSEQ);
    float t1[2];
    for (int i = 0; i < 2; i++) {
        float a = 0.f;
        for (int k = 0; k < 32; k++) a = fmaf(avg[k], se_w1[i * 32 + k], a);
        t1[i] = fmaxf(a, 0.f);
    }
    for (int k = 0; k < 32; k++) {
        float a = fmaf(t1[0], se_w2[k * 2 + 0], t1[1] * se_w2[k * 2 + 1]);
        g_gate[s * 32 + k] = sigf(a);
    }
}

// ---------------- pass 3: out-proj + gate + LN + 48-proj + transpose ---------
__global__ void __launch_bounds__(128) k_out(
    const float* __restrict__ ng, const float* __restrict__ nb,
    const float* __restrict__ proj_w, const float* __restrict__ proj_b,
    const float* __restrict__ out_w, const float* __restrict__ skip,
    float* __restrict__ out)
{
    __shared__ float sOW[DM][DI];
    __shared__ float sPW[COUT][CCH];
    __shared__ float sPB[COUT];
    __shared__ float sG1[4][16], sG2[4][16];
    int t = threadIdx.x, blk = blockIdx.x, b = blockIdx.y;
    for (int i = t; i < DM * DI; i += 128) sOW[i >> 5][i & 31] = out_w[i];
    for (int i = t; i < COUT * CCH; i += 128) {
        int o = i >> 6, c = i & 63;
        sPW[o][c] = proj_w[i] * ng[c];
    }
    if (t < COUT) {
        float a = proj_b[t];
        for (int c = 0; c < CCH; c++) a = fmaf(nb[c], proj_w[t * CCH + c], a);
        sPB[t] = a;
    }
    if (t < 64) {
        int g = t >> 4, j = t & 15, s = g * 16 + b;
        sG1[g][j] = g_gate[s * 32 + j];
        sG2[g][j] = g_gate[s * 32 + 16 + j] * skip[0];
    }
    __syncthreads();

    int l = blk * 128 + t;
    float oc[CCH];
#pragma unroll
    for (int g = 0; g < 4; g++) {
        int s = g * 16 + b;
        const float4* q4 = (const float4*)(g_q + ((size_t)s * LSEQ + l) * DI);
        float qv[32];
#pragma unroll
        for (int i = 0; i < 8; i++) {
            float4 f = q4[i];
            qv[4 * i + 0] = f.x; qv[4 * i + 1] = f.y;
            qv[4 * i + 2] = f.z; qv[4 * i + 3] = f.w;
        }
        const float4* u4 = (const float4*)(g_un + ((size_t)s * LSEQ + l) * DM);
        float uv[16];
#pragma unroll
        for (int i = 0; i < 4; i++) {
            float4 f = u4[i];
            uv[4 * i + 0] = f.x; uv[4 * i + 1] = f.y;
            uv[4 * i + 2] = f.z; uv[4 * i + 3] = f.w;
        }
#pragma unroll
        for (int j = 0; j < 16; j++) {
            float m = 0.f;
#pragma unroll
            for (int d = 0; d < DI; d++) m = fmaf(qv[d], sOW[j][d], m);
            oc[g * 16 + j] = fmaf(sG1[g][j], m, sG2[g][j] * uv[j]);
        }
    }
    float sum = 0.f, sq = 0.f;
#pragma unroll
    for (int c = 0; c < CCH; c++) { sum += oc[c]; sq = fmaf(oc[c], oc[c], sq); }
    float mean = sum * (1.f / 64.f);
    float rs = rsqrtf(sq * (1.f / 64.f) - mean * mean + 1e-5f);
#pragma unroll
    for (int c = 0; c < CCH; c++) oc[c] = (oc[c] - mean) * rs;

    float* ob = out + (size_t)b * COUT * LSEQ + l;
#pragma unroll 2
    for (int o = 0; o < COUT; o++) {
        float a = sPB[o];
#pragma unroll
        for (int c = 0; c < CCH; c++) a = fmaf(oc[c], sPW[o][c], a);
        ob[(size_t)o * LSEQ] = a;
    }
}

// ---------------- launch ------------------------------------------------------
extern "C" void kernel_launch(void* const* d_in, const int* in_sizes, int n_in,
                              void* d_out, int out_size) {
    (void)in_sizes; (void)n_in; (void)out_size;
    const float* x        = (const float*)d_in[0];
    const float* norm_g   = (const float*)d_in[1];
    const float* norm_b   = (const float*)d_in[2];
    const float* skip     = (const float*)d_in[3];
    const float* se_w1    = (const float*)d_in[4];
    const float* se_w2    = (const float*)d_in[5];
    const float* proj_w   = (const float*)d_in[6];
    const float* proj_b   = (const float*)d_in[7];
    const float* in_w     = (const float*)d_in[8];
    const float* conv_w   = (const float*)d_in[9];
    const float* conv_b   = (const float*)d_in[10];
    const float* xproj_w  = (const float*)d_in[11];
    const float* dtproj_w = (const float*)d_in[12];
    const float* dtproj_b = (const float*)d_in[13];
    const float* A_log    = (const float*)d_in[14];
    const float* Dp       = (const float*)d_in[15];
    const float* out_w    = (const float*)d_in[16];
    float* out = (float*)d_out;

    k_prep<<<1, 32>>>(A_log);
    k_ln1<<<dim3(NB1, BSZ), 128>>>(x, norm_g, norm_b);
    k_red1<<<4, 256>>>();
    k_scan<<<NSEQ * NCH / WPB, 128>>>(in_w, conv_w, conv_b, xproj_w,
                                      dtproj_w, dtproj_b, Dp);
    k_se<<<1, 64>>>(se_w1, se_w2, out_w, skip);
    k_out<<<dim3(NB1, BSZ), 128>>>(norm_g, norm_b, proj_w, proj_b, out_w,
                                   skip, out);
}

// round 4
// speedup vs baseline: 1.1679x; 1.1679x over previous
#include <cuda_runtime.h>
#include <cuda_bf16.h>
#include <cstdint>

#define BSZ  16
#define CCH  64
#define LSEQ 36864
#define DM   16
#define DI   32
#define DS   16
#define NSEQ 64
#define COUT 48

#define NCH  36
#define CSZ  1024          // LSEQ / NCH
#define WARM 64
#define TILE 16
#define WPB  4
#define NB1  288           // LSEQ / 128

// ---------------- scratch (device globals; no runtime allocation) ------------
__device__ float g_un[(size_t)NSEQ * LSEQ * DM];    // normalized grouped input
__device__ float g_q [(size_t)NSEQ * LSEQ * DI];    // pre-out-proj mamba result
__device__ float g_unpart[BSZ * NB1 * CCH];
__device__ float g_qpart [NSEQ * NCH * DI];
__device__ float g_unsum [NSEQ * DM];
__device__ float g_gate  [NSEQ * DI];
__device__ float g_A [DI * DS];
__device__ float g_a0[DI];
__device__ int   g_struct;

__device__ __forceinline__ float sigf(float v) {
    return __fdividef(1.f, 1.f + __expf(-v));
}

// ---------------- prep: A = -exp(A_log), detect power structure --------------
__global__ void k_prep(const float* __restrict__ A_log) {
    int d = threadIdx.x;  // 32 threads
    float a[DS];
#pragma unroll
    for (int n = 0; n < DS; n++) {
        a[n] = -expf(A_log[d * DS + n]);
        g_A[d * DS + n] = a[n];
    }
    g_a0[d] = a[0];
    int good = 1;
#pragma unroll
    for (int n = 0; n < DS; n++) {
        float r = a[0] * (float)(n + 1);
        if (fabsf(a[n] - r) > 1e-4f * fmaxf(1.f, fabsf(r))) good = 0;
    }
    int allok = __syncthreads_and(good);
    if (d == 0) g_struct = allok;
}

// ---------------- pass 1: layernorm + regroup + skip partial sums ------------
__global__ void __launch_bounds__(128) k_ln1(const float* __restrict__ x,
                                             const float* __restrict__ ng,
                                             const float* __restrict__ nb) {
    __shared__ float tile[CCH][129];
    __shared__ float sM[128], sR[128];
    __shared__ float sG[CCH], sB[CCH];
    int t = threadIdx.x, blk = blockIdx.x, b = blockIdx.y;
    if (t < CCH) { sG[t] = ng[t]; sB[t] = nb[t]; }

    const float* xb = x + (size_t)b * CCH * LSEQ + (size_t)blk * 128;
    float sum = 0.f, sq = 0.f;
#pragma unroll 4
    for (int c = 0; c < CCH; c++) {
        float v = xb[(size_t)c * LSEQ + t];
        tile[c][t] = v;
        sum += v;
        sq = fmaf(v, v, sq);
    }
    float mean = sum * (1.f / 64.f);
    float var  = sq * (1.f / 64.f) - mean * mean;
    sM[t] = mean;
    sR[t] = rsqrtf(var + 1e-5f);
    __syncthreads();

#pragma unroll
    for (int g = 0; g < 4; g++) {
        float* ob = g_un + ((size_t)(g * 16 + b) * LSEQ + (size_t)blk * 128) * DM;
#pragma unroll 4
        for (int rep = 0; rep < 16; rep++) {
            int idx = rep * 128 + t;
            int l = idx >> 4, j = idx & 15;
            int c = g * 16 + j;
            ob[idx] = (tile[c][l] - sM[l]) * sR[l] * sG[c] + sB[c];
        }
    }
    if (t < CCH) {
        float a = 0.f;
#pragma unroll 4
        for (int l = 0; l < 128; l++) a += (tile[t][l] - sM[l]) * sR[l];
        g_unpart[((size_t)b * NB1 + blk) * CCH + t] = a * sG[t] + 128.f * sB[t];
    }
}

// ---------------- reduce skip-path partials ----------------------------------
__global__ void k_red1() {
    int id = blockIdx.x * 256 + threadIdx.x;
    if (id >= NSEQ * DM) return;
    int s = id >> 4, j = id & 15;
    int b = s & 15, g = s >> 4;
    float a = 0.f;
    for (int blk = 0; blk < NB1; blk++)
        a += g_unpart[((size_t)b * NB1 + blk) * CCH + g * 16 + j];
    g_unsum[id] = a;
}

// ---------------- pass 2: mamba (in-proj + conv + xproj + selective scan) ----
__global__ void __launch_bounds__(128, 4) k_scan(
    const float* __restrict__ in_w,     const float* __restrict__ conv_w,
    const float* __restrict__ conv_b,   const float* __restrict__ xproj_w,
    const float* __restrict__ dtproj_w, const float* __restrict__ dtproj_b,
    const float* __restrict__ Dp)
{
    __shared__ float w_in[64][20];          // row r = in_w[r][0..15], padded
    __shared__ float w_xpB[32][36];         // row r = xproj_w[r+1][0..31], padded
    __shared__ float w0s[32];               // xproj_w row 0 (dt_raw)
    __shared__ float su  [WPB][256];        // u tile: [t][k] 16x16
    __shared__ float sAct[WPB][TILE][36];   // conv+silu output: [t][d]
    __shared__ float sBC [WPB][TILE][36];   // [t][0..15]=B, [16..31]=C, [32]=dt_raw

    int tid = threadIdx.x, wid = tid >> 5, lane = tid & 31;
    for (int i = tid; i < 64 * 16; i += 128) w_in[i >> 4][i & 15] = in_w[i];
    for (int i = tid; i < 32 * 32; i += 128) w_xpB[i >> 5][i & 31] = xproj_w[32 + i];
    if (tid < 32) w0s[tid] = xproj_w[tid];
    __syncthreads();

    int job = blockIdx.x * WPB + wid;          // 0..2303
    int s = job / NCH, ch = job - s * NCH;
    int qstart = ch * CSZ;
    int start  = (qstart >= WARM) ? (qstart - WARM) : 0;
    int nsteps = qstart + CSZ - start;         // multiple of TILE
    int woff   = qstart - start;
    const float* uBase = g_un + ((size_t)s * LSEQ + start) * DM;
    float*       qBase = g_q  + ((size_t)s * LSEQ + start) * DI;

    // per-lane (lane = d channel) constants
    float4 cwv = *(const float4*)(conv_w + lane * 4);
    float cb  = conv_b[lane];
    float dtw = dtproj_w[lane], dtb = dtproj_b[lane];
    float Dd  = Dp[lane], a0 = g_a0[lane];
    int structured = g_struct;

    float h[DS];
#pragma unroll
    for (int n = 0; n < DS; n++) h[n] = 0.f;
    float xm1 = 0.f, xm2 = 0.f, xm3 = 0.f;     // conv sliding window
    float qsum = 0.f;

    const float4* wxr = (const float4*)w_in[lane];
    const float4* wzr = (const float4*)w_in[32 + lane];

    for (int tb = 0; tb < nsteps; tb += TILE) {
        // ---- A0: stage u tile (16 t x 16 k) into smem ----
        {
            const float4* gsrc = (const float4*)(uBase + (size_t)tb * DM);
            float4* sdst = (float4*)su[wid];
            sdst[lane]      = gsrc[lane];
            sdst[lane + 32] = gsrc[lane + 32];
        }
        __syncwarp();

        // ---- A1+A2: in-proj + depthwise conv + silu  (lane = d) ----
        float act_r[TILE], zs_r[TILE];
        {
            float4 wx0 = wxr[0], wx1 = wxr[1], wx2 = wxr[2], wx3 = wxr[3];
            float4 wz0 = wzr[0], wz1 = wzr[1], wz2 = wzr[2], wz3 = wzr[3];
            const float4* su4 = (const float4*)su[wid];
#pragma unroll
            for (int t = 0; t < TILE; t++) {
                float4 u0 = su4[t * 4 + 0], u1 = su4[t * 4 + 1];
                float4 u2 = su4[t * 4 + 2], u3 = su4[t * 4 + 3];
                float ax, az;
                ax = u0.x * wx0.x;            az = u0.x * wz0.x;
                ax = fmaf(u0.y, wx0.y, ax);   az = fmaf(u0.y, wz0.y, az);
                ax = fmaf(u0.z, wx0.z, ax);   az = fmaf(u0.z, wz0.z, az);
                ax = fmaf(u0.w, wx0.w, ax);   az = fmaf(u0.w, wz0.w, az);
                ax = fmaf(u1.x, wx1.x, ax);   az = fmaf(u1.x, wz1.x, az);
                ax = fmaf(u1.y, wx1.y, ax);   az = fmaf(u1.y, wz1.y, az);
                ax = fmaf(u1.z, wx1.z, ax);   az = fmaf(u1.z, wz1.z, az);
                ax = fmaf(u1.w, wx1.w, ax);   az = fmaf(u1.w, wz1.w, az);
                ax = fmaf(u2.x, wx2.x, ax);   az = fmaf(u2.x, wz2.x, az);
                ax = fmaf(u2.y, wx2.y, ax);   az = fmaf(u2.y, wz2.y, az);
                ax = fmaf(u2.z, wx2.z, ax);   az = fmaf(u2.z, wz2.z, az);
                ax = fmaf(u2.w, wx2.w, ax);   az = fmaf(u2.w, wz2.w, az);
                ax = fmaf(u3.x, wx3.x, ax);   az = fmaf(u3.x, wz3.x, az);
                ax = fmaf(u3.y, wx3.y, ax);   az = fmaf(u3.y, wz3.y, az);
                ax = fmaf(u3.z, wx3.z, ax);   az = fmaf(u3.z, wz3.z, az);
                ax = fmaf(u3.w, wx3.w, ax);   az = fmaf(u3.w, wz3.w, az);
                // causal conv: out_t = b + w0 x_{t-3} + w1 x_{t-2} + w2 x_{t-1} + w3 x_t
                float acc = cb;
                acc = fmaf(cwv.x, xm3, acc);
                acc = fmaf(cwv.y, xm2, acc);
                acc = fmaf(cwv.z, xm1, acc);
                acc = fmaf(cwv.w, ax,  acc);
                xm3 = xm2; xm2 = xm1; xm1 = ax;
                float act = acc * sigf(acc);
                act_r[t] = act;
                sAct[wid][t][lane] = act;
                zs_r[t] = az * sigf(az);
            }
        }
        __syncwarp();

        // ---- A3: x-projection (lane = output column) ----
        {
            float o_t[TILE];
#pragma unroll
            for (int t = 0; t < TILE; t++) o_t[t] = 0.f;
#pragma unroll
            for (int db = 0; db < 8; db++) {
                float4 w4 = *(const float4*)&w_xpB[lane][db * 4];
#pragma unroll
                for (int t = 0; t < TILE; t++) {
                    float4 a4 = *(const float4*)&sAct[wid][t][db * 4];
                    float o = o_t[t];
                    o = fmaf(a4.x, w4.x, o);
                    o = fmaf(a4.y, w4.y, o);
                    o = fmaf(a4.z, w4.z, o);
                    o = fmaf(a4.w, w4.w, o);
                    o_t[t] = o;
                }
            }
#pragma unroll
            for (int t = 0; t < TILE; t++) sBC[wid][t][lane] = o_t[t];
            // dt_raw row: lanes 0..15 each handle one timestep
            if (lane < TILE) {
                float sacc = 0.f;
#pragma unroll
                for (int db = 0; db < 8; db++) {
                    float4 a4 = *(const float4*)&sAct[wid][lane][db * 4];
                    float4 w4 = *(const float4*)&w0s[db * 4];
                    sacc = fmaf(a4.x, w4.x, sacc);
                    sacc = fmaf(a4.y, w4.y, sacc);
                    sacc = fmaf(a4.z, w4.z, sacc);
                    sacc = fmaf(a4.w, w4.w, sacc);
                }
                sBC[wid][lane][32] = sacc;
            }
        }
        __syncwarp();

        // ---- B: selective scan (lane = d) ----
        {
#pragma unroll
            for (int tt = 0; tt < TILE; tt++) {
                float dtr = sBC[wid][tt][32];
                float pre = fmaf(dtr, dtw, dtb);
                float dt = (pre > 20.f) ? pre : __logf(1.f + __expf(pre));
                float xv = act_r[tt];
                float zsv = zs_r[tt];
                float bx = dt * xv;
                const float4* bc = (const float4*)&sBC[wid][tt][0];
                float4 B0 = bc[0], B1 = bc[1], B2 = bc[2], B3 = bc[3];
                float4 C0 = bc[4], C1 = bc[5], C2 = bc[6], C3 = bc[7];
                float Bv[16] = {B0.x, B0.y, B0.z, B0.w, B1.x, B1.y, B1.z, B1.w,
                                B2.x, B2.y, B2.z, B2.w, B3.x, B3.y, B3.z, B3.w};
                float Cv[16] = {C0.x, C0.y, C0.z, C0.w, C1.x, C1.y, C1.z, C1.w,
                                C2.x, C2.y, C2.z, C2.w, C3.x, C3.y, C3.z, C3.w};
                float y = 0.f;
                if (structured) {
                    float p = __expf(dt * a0);
                    float pw[16];
                    pw[0] = p;
                    pw[1] = p * p;
                    pw[2] = pw[1] * p;
#pragma unroll
                    for (int n = 3; n < 16; n++) pw[n] = pw[n - 3] * pw[2];
#pragma unroll
                    for (int n = 0; n < 16; n++) {
                        h[n] = fmaf(pw[n], h[n], bx * Bv[n]);
                        y = fmaf(h[n], Cv[n], y);
                    }
                } else {
#pragma unroll
                    for (int n = 0; n < 16; n++) {
                        h[n] = fmaf(__expf(dt * __ldg(&g_A[lane * DS + n])),
                                    h[n], bx * Bv[n]);
                        y = fmaf(h[n], Cv[n], y);
                    }
                }
                int t = tb + tt;
                if (t >= woff) {
                    float q = fmaf(Dd, xv, y) * zsv;
                    qBase[(size_t)t * DI + lane] = q;
                    qsum += q;
                }
            }
        }
        __syncwarp();
    }
    g_qpart[(s * NCH + ch) * DI + lane] = qsum;
}

// ---------------- SE gate ----------------------------------------------------
__global__ void k_se(const float* __restrict__ se_w1, const float* __restrict__ se_w2,
                     const float* __restrict__ out_w, const float* __restrict__ skip) {
    int s = threadIdx.x;
    if (s >= NSEQ) return;
    float qs[DI];
#pragma unroll 4
    for (int d = 0; d < DI; d++) {
        float a = 0.f;
        for (int ch = 0; ch < NCH; ch++) a += g_qpart[(s * NCH + ch) * DI + d];
        qs[d] = a * (1.f / (float)LSEQ);
    }
    float avg[32];
    for (int j = 0; j < 16; j++) {
        float m = 0.f;
        for (int d = 0; d < DI; d++) m = fmaf(qs[d], out_w[j * DI + d], m);
        avg[j] = m;
    }
    float sk = skip[0];
    for (int j = 0; j < 16; j++)
        avg[16 + j] = sk * g_unsum[s * 16 + j] * (1.f / (float)LSEQ);
    float t1[2];
    for (int i = 0; i < 2; i++) {
        float a = 0.f;
        for (int k = 0; k < 32; k++) a = fmaf(avg[k], se_w1[i * 32 + k], a);
        t1[i] = fmaxf(a, 0.f);
    }
    for (int k = 0; k < 32; k++) {
        float a = fmaf(t1[0], se_w2[k * 2 + 0], t1[1] * se_w2[k * 2 + 1]);
        g_gate[s * 32 + k] = sigf(a);
    }
}

// ---------------- pass 3: out-proj + gate + LN + 48-proj + transpose ---------
__global__ void __launch_bounds__(128) k_out(
    const float* __restrict__ ng, const float* __restrict__ nb,
    const float* __restrict__ proj_w, const float* __restrict__ proj_b,
    const float* __restrict__ out_w, const float* __restrict__ skip,
    float* __restrict__ out)
{
    __shared__ float sOW[DM][DI];
    __shared__ float sPW[COUT][CCH];
    __shared__ float sPB[COUT];
    __shared__ float sG1[4][16], sG2[4][16];
    int t = threadIdx.x, blk = blockIdx.x, b = blockIdx.y;
    for (int i = t; i < DM * DI; i += 128) sOW[i >> 5][i & 31] = out_w[i];
    for (int i = t; i < COUT * CCH; i += 128) {
        int o = i >> 6, c = i & 63;
        sPW[o][c] = proj_w[i] * ng[c];
    }
    if (t < COUT) {
        float a = proj_b[t];
        for (int c = 0; c < CCH; c++) a = fmaf(nb[c], proj_w[t * CCH + c], a);
        sPB[t] = a;
    }
    if (t < 64) {
        int g = t >> 4, j = t & 15, s = g * 16 + b;
        sG1[g][j] = g_gate[s * 32 + j];
        sG2[g][j] = g_gate[s * 32 + 16 + j] * skip[0];
    }
    __syncthreads();

    int l = blk * 128 + t;
    float oc[CCH];
#pragma unroll
    for (int g = 0; g < 4; g++) {
        int s = g * 16 + b;
        const float4* q4 = (const float4*)(g_q + ((size_t)s * LSEQ + l) * DI);
        float qv[32];
#pragma unroll
        for (int i = 0; i < 8; i++) {
            float4 f = q4[i];
            qv[4 * i + 0] = f.x; qv[4 * i + 1] = f.y;
            qv[4 * i + 2] = f.z; qv[4 * i + 3] = f.w;
        }
        const float4* u4 = (const float4*)(g_un + ((size_t)s * LSEQ + l) * DM);
        float uv[16];
#pragma unroll
        for (int i = 0; i < 4; i++) {
            float4 f = u4[i];
            uv[4 * i + 0] = f.x; uv[4 * i + 1] = f.y;
            uv[4 * i + 2] = f.z; uv[4 * i + 3] = f.w;
        }
#pragma unroll
        for (int j = 0; j < 16; j++) {
            float m = 0.f;
#pragma unroll
            for (int d = 0; d < DI; d++) m = fmaf(qv[d], sOW[j][d], m);
            oc[g * 16 + j] = fmaf(sG1[g][j], m, sG2[g][j] * uv[j]);
        }
    }
    float sum = 0.f, sq = 0.f;
#pragma unroll
    for (int c = 0; c < CCH; c++) { sum += oc[c]; sq = fmaf(oc[c], oc[c], sq); }
    float mean = sum * (1.f / 64.f);
    float rs = rsqrtf(sq * (1.f / 64.f) - mean * mean + 1e-5f);
#pragma unroll
    for (int c = 0; c < CCH; c++) oc[c] = (oc[c] - mean) * rs;

    float* ob = out + (size_t)b * COUT * LSEQ + l;
#pragma unroll 2
    for (int o = 0; o < COUT; o++) {
        float a = sPB[o];
#pragma unroll
        for (int c = 0; c < CCH; c++) a = fmaf(oc[c], sPW[o][c], a);
        ob[(size_t)o * LSEQ] = a;
    }
}

// ---------------- launch ------------------------------------------------------
extern "C" void kernel_launch(void* const* d_in, const int* in_sizes, int n_in,
                              void* d_out, int out_size) {
    (void)in_sizes; (void)n_in; (void)out_size;
    const float* x        = (const float*)d_in[0];
    const float* norm_g   = (const float*)d_in[1];
    const float* norm_b   = (const float*)d_in[2];
    const float* skip     = (const float*)d_in[3];
    const float* se_w1    = (const float*)d_in[4];
    const float* se_w2    = (const float*)d_in[5];
    const float* proj_w   = (const float*)d_in[6];
    const float* proj_b   = (const float*)d_in[7];
    const float* in_w     = (const float*)d_in[8];
    const float* conv_w   = (const float*)d_in[9];
    const float* conv_b   = (const float*)d_in[10];
    const float* xproj_w  = (const float*)d_in[11];
    const float* dtproj_w = (const float*)d_in[12];
    const float* dtproj_b = (const float*)d_in[13];
    const float* A_log    = (const float*)d_in[14];
    const float* Dp       = (const float*)d_in[15];
    const float* out_w    = (const float*)d_in[16];
    float* out = (float*)d_out;

    k_prep<<<1, 32>>>(A_log);
    k_ln1<<<dim3(NB1, BSZ), 128>>>(x, norm_g, norm_b);
    k_red1<<<4, 256>>>();
    k_scan<<<NSEQ * NCH / WPB, 128>>>(in_w, conv_w, conv_b, xproj_w,
                                      dtproj_w, dtproj_b, Dp);
    k_se<<<1, 64>>>(se_w1, se_w2, out_w, skip);
    k_out<<<dim3(NB1, BSZ), 128>>>(norm_g, norm_b, proj_w, proj_b, out_w,
                                   skip, out);
}

// round 10
// speedup vs baseline: 1.5310x; 1.3109x over previous
#include <cuda_runtime.h>
#include <cuda_bf16.h>
#include <cstdint>

#define BSZ  16
#define CCH  64
#define LSEQ 36864
#define DM   16
#define DI   32
#define DS   16
#define NSEQ 64
#define COUT 48

#define NCH  36
#define CSZ  1024          // LSEQ / NCH
#define WARM 64
#define TILE 16
#define WPB  4
#define NB1  288           // LSEQ / 128

// ---------------- packed f32x2 helpers (sm_103a; ptxas won't auto-fuse) ------
typedef unsigned long long f2;
__device__ __forceinline__ f2 pk2(float lo, float hi) {
    f2 r; asm("mov.b64 %0,{%1,%2};" : "=l"(r) : "f"(lo), "f"(hi)); return r;
}
__device__ __forceinline__ void up2(f2 v, float& a, float& b) {
    asm("mov.b64 {%0,%1},%2;" : "=f"(a), "=f"(b) : "l"(v));
}
__device__ __forceinline__ f2 fma2(f2 a, f2 b, f2 c) {
    f2 d; asm("fma.rn.f32x2 %0,%1,%2,%3;" : "=l"(d) : "l"(a), "l"(b), "l"(c)); return d;
}
__device__ __forceinline__ f2 mul2(f2 a, f2 b) {
    f2 d; asm("mul.rn.f32x2 %0,%1,%2;" : "=l"(d) : "l"(a), "l"(b)); return d;
}
__device__ __forceinline__ f2 add2(f2 a, f2 b) {
    f2 d; asm("add.rn.f32x2 %0,%1,%2;" : "=l"(d) : "l"(a), "l"(b)); return d;
}
__device__ __forceinline__ float hadd2(f2 v) {
    float a, b; up2(v, a, b); return a + b;
}

// ---------------- scratch (device globals; no runtime allocation) ------------
__device__ float         g_un[(size_t)NSEQ * LSEQ * DM];
__device__ __nv_bfloat16 g_q [(size_t)NSEQ * LSEQ * DI];
__device__ float g_unpart[BSZ * NB1 * CCH];
__device__ float g_qpart [NSEQ * NCH * DI];
__device__ float g_unsum [NSEQ * DM];
__device__ float g_gate  [NSEQ * DI];
__device__ float g_A [DI * DS];
__device__ float g_a0[DI];
__device__ int   g_struct;

__device__ __forceinline__ float sigf(float v) {
    return __fdividef(1.f, 1.f + __expf(-v));
}

// ---------------- prep: A = -exp(A_log), detect power structure --------------
__global__ void k_prep(const float* __restrict__ A_log) {
    int d = threadIdx.x;  // 32 threads
    float a[DS];
#pragma unroll
    for (int n = 0; n < DS; n++) {
        a[n] = -expf(A_log[d * DS + n]);
        g_A[d * DS + n] = a[n];
    }
    g_a0[d] = a[0];
    int good = 1;
#pragma unroll
    for (int n = 0; n < DS; n++) {
        float r = a[0] * (float)(n + 1);
        if (fabsf(a[n] - r) > 1e-4f * fmaxf(1.f, fabsf(r))) good = 0;
    }
    int allok = __syncthreads_and(good);
    if (d == 0) g_struct = allok;
}

// ---------------- pass 1: layernorm + regroup + skip partial sums ------------
__global__ void __launch_bounds__(128) k_ln1(const float* __restrict__ x,
                                             const float* __restrict__ ng,
                                             const float* __restrict__ nb) {
    __shared__ float tile[CCH][129];
    __shared__ float sM[128], sR[128];
    __shared__ float sG[CCH], sB[CCH];
    int t = threadIdx.x, blk = blockIdx.x, b = blockIdx.y;
    if (t < CCH) { sG[t] = ng[t]; sB[t] = nb[t]; }

    const float* xb = x + (size_t)b * CCH * LSEQ + (size_t)blk * 128;
    float sum = 0.f, sq = 0.f;
#pragma unroll 4
    for (int c = 0; c < CCH; c++) {
        float v = xb[(size_t)c * LSEQ + t];
        tile[c][t] = v;
        sum += v;
        sq = fmaf(v, v, sq);
    }
    float mean = sum * (1.f / 64.f);
    float var  = sq * (1.f / 64.f) - mean * mean;
    sM[t] = mean;
    sR[t] = rsqrtf(var + 1e-5f);
    __syncthreads();

#pragma unroll
    for (int g = 0; g < 4; g++) {
        float* ob = g_un + ((size_t)(g * 16 + b) * LSEQ + (size_t)blk * 128) * DM;
#pragma unroll 4
        for (int rep = 0; rep < 16; rep++) {
            int idx = rep * 128 + t;
            int l = idx >> 4, j = idx & 15;
            int c = g * 16 + j;
            ob[idx] = (tile[c][l] - sM[l]) * sR[l] * sG[c] + sB[c];
        }
    }
    if (t < CCH) {
        float a = 0.f;
#pragma unroll 4
        for (int l = 0; l < 128; l++) a += (tile[t][l] - sM[l]) * sR[l];
        g_unpart[((size_t)b * NB1 + blk) * CCH + t] = a * sG[t] + 128.f * sB[t];
    }
}

// ---------------- reduce skip-path partials ----------------------------------
__global__ void k_red1() {
    int id = blockIdx.x * 256 + threadIdx.x;
    if (id >= NSEQ * DM) return;
    int s = id >> 4, j = id & 15;
    int b = s & 15, g = s >> 4;
    float a = 0.f;
    for (int blk = 0; blk < NB1; blk++)
        a += g_unpart[((size_t)b * NB1 + blk) * CCH + g * 16 + j];
    g_unsum[id] = a;
}

// ---------------- pass 2: mamba (in-proj + conv + xproj + selective scan) ----
__global__ void __launch_bounds__(128, 4) k_scan(
    const float* __restrict__ in_w,     const float* __restrict__ conv_w,
    const float* __restrict__ conv_b,   const float* __restrict__ xproj_w,
    const float* __restrict__ dtproj_w, const float* __restrict__ dtproj_b,
    const float* __restrict__ Dp)
{
    __shared__ __align__(16) float w0s[32];               // xproj_w row 0
    __shared__ __align__(16) float su  [WPB][256];        // u tile [t][k]
    __shared__ __align__(16) float sAct[WPB][TILE][40];   // act [t][d]
    __shared__ __align__(16) float sZs [WPB][TILE][40];   // silu(z) [t][d]
    __shared__ __align__(16) float sBC [WPB][TILE][40];   // [0..15]=B [16..31]=C [32]=dt

    int tid = threadIdx.x, wid = tid >> 5, lane = tid & 31;
    if (tid < 32) w0s[tid] = xproj_w[tid];
    __syncthreads();

    int job = blockIdx.x * WPB + wid;          // 0..2303
    int s = job / NCH, ch = job - s * NCH;
    int qstart = ch * CSZ;
    int start  = (qstart >= WARM) ? (qstart - WARM) : 0;
    int nsteps = qstart + CSZ - start;
    int woff   = qstart - start;
    const float* uBase = g_un + ((size_t)s * LSEQ + start) * DM;
    __nv_bfloat16* qBase = g_q + ((size_t)s * LSEQ + start) * DI;

    // per-lane register-resident weights (packed pairs)
    f2 wx2[8], wz2[8], wc2[16];
    {
        const ulonglong2* wxp = (const ulonglong2*)(in_w + lane * 16);
        const ulonglong2* wzp = (const ulonglong2*)(in_w + (32 + lane) * 16);
        const ulonglong2* wcp = (const ulonglong2*)(xproj_w + 32 + lane * 32);
#pragma unroll
        for (int i = 0; i < 4; i++) {
            ulonglong2 a = wxp[i]; wx2[2 * i] = a.x; wx2[2 * i + 1] = a.y;
            ulonglong2 b = wzp[i]; wz2[2 * i] = b.x; wz2[2 * i + 1] = b.y;
        }
#pragma unroll
        for (int i = 0; i < 8; i++) {
            ulonglong2 c = wcp[i]; wc2[2 * i] = c.x; wc2[2 * i + 1] = c.y;
        }
    }
    float4 cwv = *(const float4*)(conv_w + lane * 4);
    float cb  = conv_b[lane];
    float dtw = dtproj_w[lane], dtb = dtproj_b[lane];
    float Dd  = Dp[lane], a0 = g_a0[lane];
    int structured = g_struct;

    f2 h2[8];
#pragma unroll
    for (int k = 0; k < 8; k++) h2[k] = 0ULL;
    float xm1 = 0.f, xm2 = 0.f, xm3 = 0.f;
    float qsum = 0.f;

    for (int tb = 0; tb < nsteps; tb += TILE) {
        // ---- A0: stage u tile ----
        {
            const float4* gsrc = (const float4*)(uBase + (size_t)tb * DM);
            float4* sdst = (float4*)su[wid];
            sdst[lane]      = gsrc[lane];
            sdst[lane + 32] = gsrc[lane + 32];
        }
        __syncwarp();

        // ---- A1: in-proj (packed k-pairs) + depthwise conv + silu (lane=d) --
#pragma unroll
        for (int t = 0; t < TILE; t++) {
            const ulonglong2* up = (const ulonglong2*)&su[wid][t * 16];
            ulonglong2 u0 = up[0], u1 = up[1], u2v = up[2], u3v = up[3];
            f2 ax2 = 0ULL, az2 = 0ULL;
            ax2 = fma2(u0.x, wx2[0], ax2);  az2 = fma2(u0.x, wz2[0], az2);
            ax2 = fma2(u0.y, wx2[1], ax2);  az2 = fma2(u0.y, wz2[1], az2);
            ax2 = fma2(u1.x, wx2[2], ax2);  az2 = fma2(u1.x, wz2[2], az2);
            ax2 = fma2(u1.y, wx2[3], ax2);  az2 = fma2(u1.y, wz2[3], az2);
            ax2 = fma2(u2v.x, wx2[4], ax2); az2 = fma2(u2v.x, wz2[4], az2);
            ax2 = fma2(u2v.y, wx2[5], ax2); az2 = fma2(u2v.y, wz2[5], az2);
            ax2 = fma2(u3v.x, wx2[6], ax2); az2 = fma2(u3v.x, wz2[6], az2);
            ax2 = fma2(u3v.y, wx2[7], ax2); az2 = fma2(u3v.y, wz2[7], az2);
            float ax = hadd2(ax2), az = hadd2(az2);
            float acc = cb;
            acc = fmaf(cwv.x, xm3, acc);
            acc = fmaf(cwv.y, xm2, acc);
            acc = fmaf(cwv.z, xm1, acc);
            acc = fmaf(cwv.w, ax,  acc);
            xm3 = xm2; xm2 = xm1; xm1 = ax;
            sAct[wid][t][lane] = acc * sigf(acc);
            sZs [wid][t][lane] = az * sigf(az);
        }
        __syncwarp();

        // ---- A3: x-projection (lane = output column, packed d-pairs) --------
        {
#pragma unroll
            for (int t = 0; t < TILE; t++) {
                const ulonglong2* ap = (const ulonglong2*)&sAct[wid][t][0];
                f2 o2 = 0ULL;
#pragma unroll
                for (int i = 0; i < 8; i++) {
                    ulonglong2 a = ap[i];
                    o2 = fma2(a.x, wc2[2 * i], o2);
                    o2 = fma2(a.y, wc2[2 * i + 1], o2);
                }
                sBC[wid][t][lane] = hadd2(o2);
            }
            if (lane < TILE) {
                const ulonglong2* ap = (const ulonglong2*)&sAct[wid][lane][0];
                const ulonglong2* wp = (const ulonglong2*)w0s;
                f2 s2 = 0ULL;
#pragma unroll
                for (int i = 0; i < 8; i++) {
                    ulonglong2 a = ap[i];
                    ulonglong2 w = wp[i];
                    s2 = fma2(a.x, w.x, s2);
                    s2 = fma2(a.y, w.y, s2);
                }
                sBC[wid][lane][32] = hadd2(s2);
            }
        }
        __syncwarp();

        // ---- B: selective scan (lane = d, packed n-pairs) -------------------
        if (structured) {
#pragma unroll
            for (int tt = 0; tt < TILE; tt++) {
                float dtr = sBC[wid][tt][32];
                float act = sAct[wid][tt][lane];
                float zsv = sZs[wid][tt][lane];
                float pre = fmaf(dtr, dtw, dtb);
                float dt = (pre > 20.f) ? pre : __logf(1.f + __expf(pre));
                float bx = dt * act;
                f2 bx2 = pk2(bx, bx);
                float p = __expf(dt * a0);
                float pq = p * p;
                f2 Q = pk2(pq, pq);
                f2 pw = pk2(p, pq);
                const ulonglong2* bp = (const ulonglong2*)&sBC[wid][tt][0];
                ulonglong2 Bq0 = bp[0], Bq1 = bp[1], Bq2 = bp[2], Bq3 = bp[3];
                ulonglong2 Cq0 = bp[4], Cq1 = bp[5], Cq2 = bp[6], Cq3 = bp[7];
                f2 Bv[8] = {Bq0.x, Bq0.y, Bq1.x, Bq1.y, Bq2.x, Bq2.y, Bq3.x, Bq3.y};
                f2 Cv[8] = {Cq0.x, Cq0.y, Cq1.x, Cq1.y, Cq2.x, Cq2.y, Cq3.x, Cq3.y};
                f2 y2 = 0ULL;
#pragma unroll
                for (int k = 0; k < 8; k++) {
                    h2[k] = fma2(pw, h2[k], mul2(bx2, Bv[k]));
                    y2 = fma2(h2[k], Cv[k], y2);
                    pw = mul2(pw, Q);
                }
                int t = tb + tt;
                if (t >= woff) {
                    float q = fmaf(Dd, act, hadd2(y2)) * zsv;
                    qBase[(size_t)t * DI + lane] = __float2bfloat16(q);
                    qsum += q;
                }
            }
        } else {
#pragma unroll 2
            for (int tt = 0; tt < TILE; tt++) {
                float dtr = sBC[wid][tt][32];
                float act = sAct[wid][tt][lane];
                float zsv = sZs[wid][tt][lane];
                float pre = fmaf(dtr, dtw, dtb);
                float dt = (pre > 20.f) ? pre : __logf(1.f + __expf(pre));
                float bx = dt * act;
                float y = 0.f;
#pragma unroll
                for (int k = 0; k < 8; k++) {
                    float hlo, hhi;
                    up2(h2[k], hlo, hhi);
                    float Blo = sBC[wid][tt][2 * k],     Bhi = sBC[wid][tt][2 * k + 1];
                    float Clo = sBC[wid][tt][16 + 2 * k], Chi = sBC[wid][tt][17 + 2 * k];
                    hlo = fmaf(__expf(dt * g_A[lane * DS + 2 * k]),     hlo, bx * Blo);
                    hhi = fmaf(__expf(dt * g_A[lane * DS + 2 * k + 1]), hhi, bx * Bhi);
                    y = fmaf(hlo, Clo, y);
                    y = fmaf(hhi, Chi, y);
                    h2[k] = pk2(hlo, hhi);
                }
                int t = tb + tt;
                if (t >= woff) {
                    float q = fmaf(Dd, act, y) * zsv;
                    qBase[(size_t)t * DI + lane] = __float2bfloat16(q);
                    qsum += q;
                }
            }
        }
        __syncwarp();
    }
    g_qpart[(s * NCH + ch) * DI + lane] = qsum;
}

// ---------------- SE gate ----------------------------------------------------
__global__ void k_se(const float* __restrict__ se_w1, const float* __restrict__ se_w2,
                     const float* __restrict__ out_w, const float* __restrict__ skip) {
    int s = threadIdx.x;
    if (s >= NSEQ) return;
    float qs[DI];
#pragma unroll 4
    for (int d = 0; d < DI; d++) {
        float a = 0.f;
        for (int ch = 0; ch < NCH; ch++) a += g_qpart[(s * NCH + ch) * DI + d];
        qs[d] = a * (1.f / (float)LSEQ);
    }
    float avg[32];
    for (int j = 0; j < 16; j++) {
        float m = 0.f;
        for (int d = 0; d < DI; d++) m = fmaf(qs[d], out_w[j * DI + d], m);
        avg[j] = m;
    }
    float sk = skip[0];
    for (int j = 0; j < 16; j++)
        avg[16 + j] = sk * g_unsum[s * 16 + j] * (1.f / (float)LSEQ);
    float t1[2];
    for (int i = 0; i < 2; i++) {
        float a = 0.f;
        for (int k = 0; k < 32; k++) a = fmaf(avg[k], se_w1[i * 32 + k], a);
        t1[i] = fmaxf(a, 0.f);
    }
    for (int k = 0; k < 32; k++) {
        float a = fmaf(t1[0], se_w2[k * 2 + 0], t1[1] * se_w2[k * 2 + 1]);
        g_gate[s * 32 + k] = sigf(a);
    }
}

// ---------------- pass 3: out-proj + gate + LN + 48-proj + transpose ---------
__global__ void __launch_bounds__(128) k_out(
    const float* __restrict__ ng, const float* __restrict__ nb,
    const float* __restrict__ proj_w, const float* __restrict__ proj_b,
    const float* __restrict__ out_w, const float* __restrict__ skip,
    float* __restrict__ out)
{
    __shared__ __align__(16) float sOW[DM][DI];
    __shared__ __align__(16) float sPW[COUT][CCH];
    __shared__ float sPB[COUT];
    __shared__ float sG1[4][16], sG2[4][16];
    int t = threadIdx.x, blk = blockIdx.x, b = blockIdx.y;
    for (int i = t; i < DM * DI; i += 128) sOW[i >> 5][i & 31] = out_w[i];
    for (int i = t; i < COUT * CCH; i += 128) {
        int o = i >> 6, c = i & 63;
        sPW[o][c] = proj_w[i] * ng[c];
    }
    if (t < COUT) {
        float a = proj_b[t];
        for (int c = 0; c < CCH; c++) a = fmaf(nb[c], proj_w[t * CCH + c], a);
        sPB[t] = a;
    }
    if (t < 64) {
        int g = t >> 4, j = t & 15, s = g * 16 + b;
        sG1[g][j] = g_gate[s * 32 + j];
        sG2[g][j] = g_gate[s * 32 + 16 + j] * skip[0];
    }
    __syncthreads();

    int l = blk * 128 + t;
    float ocs[CCH];
#pragma unroll
    for (int g = 0; g < 4; g++) {
        int s = g * 16 + b;
        // q (bf16, 32 values) -> 16 packed f32x2 pairs
        const __nv_bfloat162* qh =
            (const __nv_bfloat162*)(g_q + ((size_t)s * LSEQ + l) * DI);
        f2 q2[16];
#pragma unroll
        for (int i = 0; i < 16; i++) {
            float2 f = __bfloat1622float2(qh[i]);
            q2[i] = pk2(f.x, f.y);
        }
        const float4* u4 = (const float4*)(g_un + ((size_t)s * LSEQ + l) * DM);
        float uv[16];
#pragma unroll
        for (int i = 0; i < 4; i++) {
            float4 f = u4[i];
            uv[4 * i + 0] = f.x; uv[4 * i + 1] = f.y;
            uv[4 * i + 2] = f.z; uv[4 * i + 3] = f.w;
        }
#pragma unroll
        for (int j = 0; j < 16; j++) {
            const ulonglong2* wp = (const ulonglong2*)sOW[j];
            f2 m2 = 0ULL;
#pragma unroll
            for (int i = 0; i < 8; i++) {
                ulonglong2 w = wp[i];
                m2 = fma2(q2[2 * i], w.x, m2);
                m2 = fma2(q2[2 * i + 1], w.y, m2);
            }
            ocs[g * 16 + j] = fmaf(sG1[g][j], hadd2(m2), sG2[g][j] * uv[j]);
        }
    }
    // LN over 64 channels (packed)
    f2 oc2[32];
#pragma unroll
    for (int p = 0; p < 32; p++) oc2[p] = pk2(ocs[2 * p], ocs[2 * p + 1]);
    f2 s2 = 0ULL, v2 = 0ULL;
#pragma unroll
    for (int p = 0; p < 32; p++) {
        s2 = add2(s2, oc2[p]);
        v2 = fma2(oc2[p], oc2[p], v2);
    }
    float mean = hadd2(s2) * (1.f / 64.f);
    float rs = rsqrtf(hadd2(v2) * (1.f / 64.f) - mean * mean + 1e-5f);
    f2 rs2 = pk2(rs, rs);
    f2 mb2 = pk2(-mean * rs, -mean * rs);
#pragma unroll
    for (int p = 0; p < 32; p++) oc2[p] = fma2(oc2[p], rs2, mb2);

    float* ob = out + (size_t)b * COUT * LSEQ + l;
#pragma unroll 2
    for (int o = 0; o < COUT; o++) {
        const ulonglong2* wp = (const ulonglong2*)sPW[o];
        f2 acc2 = 0ULL;
#pragma unroll
        for (int i = 0; i < 16; i++) {
            ulonglong2 w = wp[i];
            acc2 = fma2(oc2[2 * i], w.x, acc2);
            acc2 = fma2(oc2[2 * i + 1], w.y, acc2);
        }
        ob[(size_t)o * LSEQ] = hadd2(acc2) + sPB[o];
    }
}

// ---------------- launch ------------------------------------------------------
extern "C" void kernel_launch(void* const* d_in, const int* in_sizes, int n_in,
                              void* d_out, int out_size) {
    (void)in_sizes; (void)n_in; (void)out_size;
    const float* x        = (const float*)d_in[0];
    const float* norm_g   = (const float*)d_in[1];
    const float* norm_b   = (const float*)d_in[2];
    const float* skip     = (const float*)d_in[3];
    const float* se_w1    = (const float*)d_in[4];
    const float* se_w2    = (const float*)d_in[5];
    const float* proj_w   = (const float*)d_in[6];
    const float* proj_b   = (const float*)d_in[7];
    const float* in_w     = (const float*)d_in[8];
    const float* conv_w   = (const float*)d_in[9];
    const float* conv_b   = (const float*)d_in[10];
    const float* xproj_w  = (const float*)d_in[11];
    const float* dtproj_w = (const float*)d_in[12];
    const float* dtproj_b = (const float*)d_in[13];
    const float* A_log    = (const float*)d_in[14];
    const float* Dp       = (const float*)d_in[15];
    const float* out_w    = (const float*)d_in[16];
    float* out = (float*)d_out;

    k_prep<<<1, 32>>>(A_log);
    k_ln1<<<dim3(NB1, BSZ), 128>>>(x, norm_g, norm_b);
    k_red1<<<4, 256>>>();
    k_scan<<<NSEQ * NCH / WPB, 128>>>(in_w, conv_w, conv_b, xproj_w,
                                      dtproj_w, dtproj_b, Dp);
    k_se<<<1, 64>>>(se_w1, se_w2, out_w, skip);
    k_out<<<dim3(NB1, BSZ), 128>>>(norm_g, norm_b, proj_w, proj_b, out_w,
                                   skip, out);
}